// round 1
// baseline (speedup 1.0000x reference)
#include <cuda_runtime.h>
#include <cstdint>

// Problem constants (fixed shapes)
#define NN 50000      // nodes
#define EE 1600000    // edges
#define TT 6          // time steps
#define NB 8          // batch
#define NH 16         // hidden

// Scratch (device globals — no allocation allowed)
__device__ int          g_deg[NN];
__device__ float        g_dinv[NN];
__device__ float4       g_xt[NN * 2];    // x[b, T-1, n] transposed to [n][8]
__device__ float4       g_gt[NN * 2];    // dinv[n] * xt[n][b]
__device__ float4       g_acc[NN * 2];   // scatter accumulator [n][8]
__device__ float        g_bsum[NB * NH]; // per-(b,h) node sums
__device__ unsigned int g_cnt;

// ---------------------------------------------------------------------------
// K0: zero scratch
__global__ void k_zero() {
    int i = blockIdx.x * blockDim.x + threadIdx.x;
    int stride = gridDim.x * blockDim.x;
    for (int j = i; j < NN; j += stride) g_deg[j] = 0;
    float4 z = make_float4(0.f, 0.f, 0.f, 0.f);
    for (int j = i; j < NN * 2; j += stride) g_acc[j] = z;
    if (i < NB * NH) g_bsum[i] = 0.f;
    if (i == 0) g_cnt = 0u;
}

// ---------------------------------------------------------------------------
// K1: degree histogram (src column) + transpose last-timestep x to [n][8]
__global__ void k_deg_xt(const int* __restrict__ ei, const float* __restrict__ x) {
    int i = blockIdx.x * blockDim.x + threadIdx.x;
    int stride = gridDim.x * blockDim.x;

    const int4* s4 = (const int4*)ei;  // src = ei[0..EE)
    for (int j = i; j < EE / 4; j += stride) {
        int4 s = s4[j];
        atomicAdd(&g_deg[s.x], 1);
        atomicAdd(&g_deg[s.y], 1);
        atomicAdd(&g_deg[s.z], 1);
        atomicAdd(&g_deg[s.w], 1);
    }

    // x layout: [B, T, N]; take t = T-1 slice for each b
    const float* xl = x + (TT - 1) * NN;
    for (int n = i; n < NN; n += stride) {
        float v0 = xl[0 * TT * NN + n];
        float v1 = xl[1 * TT * NN + n];
        float v2 = xl[2 * TT * NN + n];
        float v3 = xl[3 * TT * NN + n];
        float v4 = xl[4 * TT * NN + n];
        float v5 = xl[5 * TT * NN + n];
        float v6 = xl[6 * TT * NN + n];
        float v7 = xl[7 * TT * NN + n];
        g_xt[2 * n]     = make_float4(v0, v1, v2, v3);
        g_xt[2 * n + 1] = make_float4(v4, v5, v6, v7);
    }
}

// ---------------------------------------------------------------------------
// K2: dinv = rsqrt(deg) (0 if deg==0); gt = dinv * xt
__global__ void k_dinv() {
    int i = blockIdx.x * blockDim.x + threadIdx.x;
    int stride = gridDim.x * blockDim.x;
    for (int n = i; n < NN; n += stride) {
        int d = g_deg[n];
        float dv = (d > 0) ? rsqrtf((float)d) : 0.f;
        g_dinv[n] = dv;
        float4 a = g_xt[2 * n];
        float4 b = g_xt[2 * n + 1];
        a.x *= dv; a.y *= dv; a.z *= dv; a.w *= dv;
        b.x *= dv; b.y *= dv; b.z *= dv; b.w *= dv;
        g_gt[2 * n]     = a;
        g_gt[2 * n + 1] = b;
    }
}

// ---------------------------------------------------------------------------
// K3: main edge scatter: acc[dst][0..7] += gt[src][0..7] via vector RED
__device__ __forceinline__ void red_add_v4(float4* addr, float4 v) {
    asm volatile("red.global.add.v4.f32 [%0], {%1, %2, %3, %4};"
                 :: "l"(addr), "f"(v.x), "f"(v.y), "f"(v.z), "f"(v.w)
                 : "memory");
}

__global__ void k_scatter(const int* __restrict__ ei) {
    int i = blockIdx.x * blockDim.x + threadIdx.x;
    int stride = gridDim.x * blockDim.x;
    const int4* s4 = (const int4*)ei;         // src
    const int4* d4 = (const int4*)(ei + EE);  // dst
    for (int j = i; j < EE / 4; j += stride) {
        int4 s = s4[j];
        int4 d = d4[j];
        {
            float4 a = __ldg(&g_gt[2 * s.x]), b = __ldg(&g_gt[2 * s.x + 1]);
            red_add_v4(&g_acc[2 * d.x], a); red_add_v4(&g_acc[2 * d.x + 1], b);
        }
        {
            float4 a = __ldg(&g_gt[2 * s.y]), b = __ldg(&g_gt[2 * s.y + 1]);
            red_add_v4(&g_acc[2 * d.y], a); red_add_v4(&g_acc[2 * d.y + 1], b);
        }
        {
            float4 a = __ldg(&g_gt[2 * s.z]), b = __ldg(&g_gt[2 * s.z + 1]);
            red_add_v4(&g_acc[2 * d.z], a); red_add_v4(&g_acc[2 * d.z + 1], b);
        }
        {
            float4 a = __ldg(&g_gt[2 * s.w]), b = __ldg(&g_gt[2 * s.w + 1]);
            red_add_v4(&g_acc[2 * d.w], a); red_add_v4(&g_acc[2 * d.w + 1], b);
        }
    }
}

// ---------------------------------------------------------------------------
// K4: gate math + reduction over nodes + final linear head (last-block trick)
__global__ void k_combine(const float* __restrict__ wxz, const float* __restrict__ bxz,
                          const float* __restrict__ bhz, const float* __restrict__ wxh,
                          const float* __restrict__ bxh, const float* __restrict__ bhh,
                          const float* __restrict__ wlin, const float* __restrict__ blin,
                          float* __restrict__ out) {
    __shared__ float sw0z[NH], sw1z[NH], sbz[NH], sw0h[NH], sw1h[NH], sbh[NH];
    int t = threadIdx.x;
    if (t < NH) {
        sw0z[t] = wxz[t];       sw1z[t] = wxz[NH + t];  sbz[t] = bxz[t] + bhz[t];
        sw0h[t] = wxh[t];       sw1h[t] = wxh[NH + t];  sbh[t] = bxh[t] + bhh[t];
    }
    __syncthreads();

    float accv[NH];
#pragma unroll
    for (int h = 0; h < NH; h++) accv[h] = 0.f;

    const float* xt = (const float*)g_xt;
    const float* ac = (const float*)g_acc;

    int i = blockIdx.x * blockDim.x + t;
    int stride = gridDim.x * blockDim.x;  // multiple of 8 -> b = i & 7 fixed per thread
    for (int idx = i; idx < NN * NB; idx += stride) {
        int n = idx >> 3;
        float xv = xt[idx];
        float lxv = -g_dinv[n] * ac[idx];
#pragma unroll
        for (int h = 0; h < NH; h++) {
            float za = fmaf(xv, sw0z[h], fmaf(lxv, sw1z[h], sbz[h]));
            float ha = fmaf(xv, sw0h[h], fmaf(lxv, sw1h[h], sbh[h]));
            // (1 - sigmoid(za)) = 1/(1+e^{za})
            float one_m_z = __fdividef(1.f, 1.f + __expf(za));
            // tanh(ha) = 1 - 2/(e^{2ha}+1)
            float ht = 1.f - __fdividef(2.f, __expf(2.f * ha) + 1.f);
            accv[h] += one_m_z * ht;
        }
    }

    // warp reduce across lanes with the same b = lane & 7
#pragma unroll
    for (int h = 0; h < NH; h++) {
        accv[h] += __shfl_xor_sync(0xffffffffu, accv[h], 8);
        accv[h] += __shfl_xor_sync(0xffffffffu, accv[h], 16);
    }

    __shared__ float sred[8][NB * NH];  // 8 warps x 128
    int warp = t >> 5, lane = t & 31;
    if (lane < NB) {
#pragma unroll
        for (int h = 0; h < NH; h++) sred[warp][lane * NH + h] = accv[h];
    }
    __syncthreads();

    if (t < NB * NH) {
        float s = 0.f;
#pragma unroll
        for (int w = 0; w < 8; w++) s += sred[w][t];
        atomicAdd(&g_bsum[t], s);
        __threadfence();
    }
    __syncthreads();

    __shared__ unsigned int s_last;
    if (t == 0) {
        __threadfence();
        s_last = (atomicAdd(&g_cnt, 1u) == gridDim.x - 1) ? 1u : 0u;
    }
    __syncthreads();

    if (s_last && t < NB) {
        const float inv_n = 1.f / (float)NN;
        float s = 0.f;
#pragma unroll
        for (int h = 0; h < NH; h++) {
            float m = __ldcg(&g_bsum[t * NH + h]) * inv_n;
            s += fmaxf(m, 0.f) * wlin[h];
        }
        out[t] = s + blin[0];
    }
}

// ---------------------------------------------------------------------------
extern "C" void kernel_launch(void* const* d_in, const int* in_sizes, int n_in,
                              void* d_out, int out_size) {
    const float* x    = (const float*)d_in[0];  // [B,T,N,1]
    const int*   ei   = (const int*)d_in[1];    // [2,E]
    const float* wxz  = (const float*)d_in[2];  // [2,16]
    const float* bxz  = (const float*)d_in[3];
    const float* bhz  = (const float*)d_in[4];
    const float* wxh  = (const float*)d_in[5];
    const float* bxh  = (const float*)d_in[6];
    const float* bhh  = (const float*)d_in[7];
    const float* wlin = (const float*)d_in[8];  // [1,16]
    const float* blin = (const float*)d_in[9];  // [1]
    float* out = (float*)d_out;                 // [8]

    k_zero<<<128, 256>>>();
    k_deg_xt<<<1184, 256>>>(ei, x);
    k_dinv<<<196, 256>>>();
    k_scatter<<<(EE / 4 + 255) / 256, 256>>>(ei);
    k_combine<<<592, 256>>>(wxz, bxz, bhz, wxh, bxh, bhh, wlin, blin, out);
}

// round 3
// speedup vs baseline: 1.2465x; 1.2465x over previous
#include <cuda_runtime.h>
#include <cuda_fp16.h>
#include <cstdint>

// Problem constants (fixed shapes)
#define NN 50000      // nodes
#define EE 1600000    // edges
#define TT 6          // time steps
#define NB 8          // batch
#define NH 16         // hidden

// Scratch (device globals — no allocation allowed)
__device__ int          g_deg[NN];
__device__ float        g_dinv[NN];
__device__ float4       g_xt[NN * 2];    // x[b, T-1, n] transposed to [n][8] (fp32, for combine)
__device__ uint4        g_gth[NN];       // dinv[n] * xt[n][b], packed 8 x f16
__device__ uint4        g_acch[NN];      // scatter accumulator, 8 x f16 per node
__device__ float        g_bsum[NB * NH]; // per-(b,h) node sums
__device__ unsigned int g_cnt;

// ---------------------------------------------------------------------------
__device__ __forceinline__ float tanh_fast(float x) {
    float y;
    asm("tanh.approx.f32 %0, %1;" : "=f"(y) : "f"(x));
    return y;
}

__device__ __forceinline__ void red_add_v4h2(uint4* addr, uint4 v) {
    asm volatile("red.global.add.noftz.v4.f16x2 [%0], {%1, %2, %3, %4};"
                 :: "l"(addr), "r"(v.x), "r"(v.y), "r"(v.z), "r"(v.w)
                 : "memory");
}

// ---------------------------------------------------------------------------
// K0: zero scratch
__global__ void k_zero() {
    int i = blockIdx.x * blockDim.x + threadIdx.x;
    int stride = gridDim.x * blockDim.x;
    uint4 z4 = make_uint4(0u, 0u, 0u, 0u);
    for (int j = i; j < NN; j += stride) {
        g_deg[j] = 0;
        g_acch[j] = z4;
    }
    if (i < NB * NH) g_bsum[i] = 0.f;
    if (i == 0) g_cnt = 0u;
}

// ---------------------------------------------------------------------------
// K1: degree histogram (src column) + transpose last-timestep x to [n][8]
__global__ void k_deg_xt(const int* __restrict__ ei, const float* __restrict__ x) {
    int i = blockIdx.x * blockDim.x + threadIdx.x;
    int stride = gridDim.x * blockDim.x;

    const int4* s4 = (const int4*)ei;  // src = ei[0..EE)
    for (int j = i; j < EE / 4; j += stride) {
        int4 s = __ldcs(&s4[j]);
        atomicAdd(&g_deg[s.x], 1);
        atomicAdd(&g_deg[s.y], 1);
        atomicAdd(&g_deg[s.z], 1);
        atomicAdd(&g_deg[s.w], 1);
    }

    // x layout: [B, T, N]; take t = T-1 slice for each b
    const float* xl = x + (TT - 1) * NN;
    for (int n = i; n < NN; n += stride) {
        float v0 = xl[0 * TT * NN + n];
        float v1 = xl[1 * TT * NN + n];
        float v2 = xl[2 * TT * NN + n];
        float v3 = xl[3 * TT * NN + n];
        float v4 = xl[4 * TT * NN + n];
        float v5 = xl[5 * TT * NN + n];
        float v6 = xl[6 * TT * NN + n];
        float v7 = xl[7 * TT * NN + n];
        g_xt[2 * n]     = make_float4(v0, v1, v2, v3);
        g_xt[2 * n + 1] = make_float4(v4, v5, v6, v7);
    }
}

// ---------------------------------------------------------------------------
// K2: dinv = rsqrt(deg) (0 if deg==0); gth = f16(dinv * xt)
__global__ void k_dinv() {
    int i = blockIdx.x * blockDim.x + threadIdx.x;
    int stride = gridDim.x * blockDim.x;
    for (int n = i; n < NN; n += stride) {
        int d = g_deg[n];
        float dv = (d > 0) ? rsqrtf((float)d) : 0.f;
        g_dinv[n] = dv;
        float4 a = g_xt[2 * n];
        float4 b = g_xt[2 * n + 1];
        __half2 h0 = __floats2half2_rn(a.x * dv, a.y * dv);
        __half2 h1 = __floats2half2_rn(a.z * dv, a.w * dv);
        __half2 h2 = __floats2half2_rn(b.x * dv, b.y * dv);
        __half2 h3 = __floats2half2_rn(b.z * dv, b.w * dv);
        uint4 p;
        p.x = *(unsigned int*)&h0;
        p.y = *(unsigned int*)&h1;
        p.z = *(unsigned int*)&h2;
        p.w = *(unsigned int*)&h3;
        g_gth[n] = p;
    }
}

// ---------------------------------------------------------------------------
// K3: main edge scatter: acc[dst][0..7] += gt[src][0..7] via one 16B f16x2 RED
__global__ void k_scatter(const int* __restrict__ ei) {
    int i = blockIdx.x * blockDim.x + threadIdx.x;
    int stride = gridDim.x * blockDim.x;
    const int4* s4 = (const int4*)ei;         // src
    const int4* d4 = (const int4*)(ei + EE);  // dst
    for (int j = i; j < EE / 4; j += stride) {
        int4 s = __ldcs(&s4[j]);
        int4 d = __ldcs(&d4[j]);
        uint4 a0 = __ldg(&g_gth[s.x]);
        uint4 a1 = __ldg(&g_gth[s.y]);
        uint4 a2 = __ldg(&g_gth[s.z]);
        uint4 a3 = __ldg(&g_gth[s.w]);
        red_add_v4h2(&g_acch[d.x], a0);
        red_add_v4h2(&g_acch[d.y], a1);
        red_add_v4h2(&g_acch[d.z], a2);
        red_add_v4h2(&g_acch[d.w], a3);
    }
}

// ---------------------------------------------------------------------------
// K4: gate math + reduction over nodes + final linear head (last-block trick)
__global__ void k_combine(const float* __restrict__ wxz, const float* __restrict__ bxz,
                          const float* __restrict__ bhz, const float* __restrict__ wxh,
                          const float* __restrict__ bxh, const float* __restrict__ bhh,
                          const float* __restrict__ wlin, const float* __restrict__ blin,
                          float* __restrict__ out) {
    __shared__ float sw0z[NH], sw1z[NH], sbz[NH], sw0h[NH], sw1h[NH], sbh[NH];
    int t = threadIdx.x;
    if (t < NH) {
        sw0z[t] = wxz[t];       sw1z[t] = wxz[NH + t];  sbz[t] = bxz[t] + bhz[t];
        sw0h[t] = wxh[t];       sw1h[t] = wxh[NH + t];  sbh[t] = bxh[t] + bhh[t];
    }
    __syncthreads();

    float accv[NH];
#pragma unroll
    for (int h = 0; h < NH; h++) accv[h] = 0.f;

    const float*  xt = (const float*)g_xt;
    const __half* ac = (const __half*)g_acch;

    int i = blockIdx.x * blockDim.x + t;
    int stride = gridDim.x * blockDim.x;  // multiple of 8 -> b = i & 7 fixed per thread
    for (int idx = i; idx < NN * NB; idx += stride) {
        int n = idx >> 3;
        float xv = xt[idx];
        float lxv = -g_dinv[n] * __half2float(ac[idx]);
#pragma unroll
        for (int h = 0; h < NH; h++) {
            float za = fmaf(xv, sw0z[h], fmaf(lxv, sw1z[h], sbz[h]));
            float ha = fmaf(xv, sw0h[h], fmaf(lxv, sw1h[h], sbh[h]));
            // 1 - sigmoid(za) = 0.5 - 0.5*tanh(za/2)
            float one_m_z = fmaf(-0.5f, tanh_fast(0.5f * za), 0.5f);
            float ht = tanh_fast(ha);
            accv[h] += one_m_z * ht;
        }
    }

    // warp reduce across lanes with the same b = lane & 7
#pragma unroll
    for (int h = 0; h < NH; h++) {
        accv[h] += __shfl_xor_sync(0xffffffffu, accv[h], 8);
        accv[h] += __shfl_xor_sync(0xffffffffu, accv[h], 16);
    }

    __shared__ float sred[8][NB * NH];  // 8 warps x 128
    int warp = t >> 5, lane = t & 31;
    if (lane < NB) {
#pragma unroll
        for (int h = 0; h < NH; h++) sred[warp][lane * NH + h] = accv[h];
    }
    __syncthreads();

    if (t < NB * NH) {
        float s = 0.f;
#pragma unroll
        for (int w = 0; w < 8; w++) s += sred[w][t];
        atomicAdd(&g_bsum[t], s);
        __threadfence();
    }
    __syncthreads();

    __shared__ unsigned int s_last;
    if (t == 0) {
        __threadfence();
        s_last = (atomicAdd(&g_cnt, 1u) == gridDim.x - 1) ? 1u : 0u;
    }
    __syncthreads();

    if (s_last && t < NB) {
        const float inv_n = 1.f / (float)NN;
        float s = 0.f;
#pragma unroll
        for (int h = 0; h < NH; h++) {
            float m = __ldcg(&g_bsum[t * NH + h]) * inv_n;
            s += fmaxf(m, 0.f) * wlin[h];
        }
        out[t] = s + blin[0];
    }
}

// ---------------------------------------------------------------------------
extern "C" void kernel_launch(void* const* d_in, const int* in_sizes, int n_in,
                              void* d_out, int out_size) {
    const float* x    = (const float*)d_in[0];  // [B,T,N,1]
    const int*   ei   = (const int*)d_in[1];    // [2,E]
    const float* wxz  = (const float*)d_in[2];  // [2,16]
    const float* bxz  = (const float*)d_in[3];
    const float* bhz  = (const float*)d_in[4];
    const float* wxh  = (const float*)d_in[5];
    const float* bxh  = (const float*)d_in[6];
    const float* bhh  = (const float*)d_in[7];
    const float* wlin = (const float*)d_in[8];  // [1,16]
    const float* blin = (const float*)d_in[9];  // [1]
    float* out = (float*)d_out;                 // [8]

    k_zero<<<128, 256>>>();
    k_deg_xt<<<1184, 256>>>(ei, x);
    k_dinv<<<196, 256>>>();
    k_scatter<<<1184, 256>>>(ei);
    k_combine<<<592, 256>>>(wxz, bxz, bhz, wxh, bxh, bhh, wlin, blin, out);
}